// round 14
// baseline (speedup 1.0000x reference)
#include <cuda_runtime.h>
#include <cuda_fp16.h>
#include <cstdint>
#include <cstddef>

#define NB 64
#define NT 512
#define NH 1024
#define GRID2 128

#define GATE_STRIDE 33554432u  // 512*64*1024

__device__ float    g_gates[4u * GATE_STRIDE];  // [gate][t][b][h]
__device__ unsigned g_hA[2][NB * NH / 2];       // h as fp16 pairs, MMA-fragment order
__device__ unsigned g_flags[GRID2 * 8];         // per-CTA warp-arrival counter: 16*(t+1) when h(t+1) ready
__device__ unsigned g_rd[GRID2 * 8];            // per-CTA warp-arrival counter: 16*(t+1) when h(t) fully read
__device__ unsigned g_xh[16777216];             // x as half2 (33.5M halves, row-major)
__device__ unsigned g_Wh[2097152];              // W_x as half2 k-pairs: [gate][k2:512][n:1024]

__device__ __forceinline__ unsigned h2u(__half2 h) {
    unsigned u;
    __builtin_memcpy(&u, &h, 4);
    return u;
}

// fp16 m16n8k16
__device__ __forceinline__ void mma16(float c[4], const unsigned a[4], const unsigned b[2]) {
    asm volatile(
        "mma.sync.aligned.m16n8k16.row.col.f32.f16.f16.f32 "
        "{%0,%1,%2,%3},{%4,%5,%6,%7},{%8,%9},{%0,%1,%2,%3};\n"
        : "+f"(c[0]), "+f"(c[1]), "+f"(c[2]), "+f"(c[3])
        : "r"(a[0]), "r"(a[1]), "r"(a[2]), "r"(a[3]), "r"(b[0]), "r"(b[1]));
}

__device__ __forceinline__ void cp16(unsigned dst, const void* src) {
    asm volatile("cp.async.ca.shared.global [%0], [%1], 16;\n" :: "r"(dst), "l"(src));
}

__device__ __forceinline__ unsigned ld_acq(const unsigned* p) {
    unsigned v;
    asm volatile("ld.acquire.gpu.global.u32 %0, [%1];" : "=r"(v) : "l"(p) : "memory");
    return v;
}

__device__ __forceinline__ void red_rel(unsigned* p, unsigned v) {
    asm volatile("red.release.gpu.global.add.u32 [%0], %1;" :: "l"(p), "r"(v) : "memory");
}

__device__ __forceinline__ float sig_f(float z) {
    return __fdividef(1.0f, 1.0f + __expf(-z));
}
__device__ __forceinline__ float tanh_f(float z) {
    return __fdividef(2.0f, 1.0f + __expf(-2.0f * z)) - 1.0f;
}

// ---------------------------------------------------------------------------
// Phase 0: convert x and W_x to fp16 scratch; per-replay init.
// ---------------------------------------------------------------------------
__global__ void __launch_bounds__(256) lstm_conv(
    const float* __restrict__ x,
    const float* __restrict__ Wxi, const float* __restrict__ Wxf,
    const float* __restrict__ Wxc, const float* __restrict__ Wxo)
{
    const int tid    = blockIdx.x * blockDim.x + threadIdx.x;
    const int stride = gridDim.x * blockDim.x;

    const float2* x2 = (const float2*)x;
#pragma unroll 4
    for (int i = tid; i < 16777216; i += stride) {
        float2 v = x2[i];
        g_xh[i] = h2u(__floats2half2_rn(v.x, v.y));
    }

    for (int i = tid; i < 2097152; i += stride) {
        int g  = i >> 19;
        int r  = i & 524287;
        int k2 = r >> 10;
        int n  = r & 1023;
        const float* W = (g == 0) ? Wxi : (g == 1) ? Wxf : (g == 2) ? Wxc : Wxo;
        float lo = W[(size_t)(2 * k2) * 1024 + n];
        float hi = W[(size_t)(2 * k2 + 1) * 1024 + n];
        g_Wh[i] = h2u(__floats2half2_rn(lo, hi));
    }

    // per-replay init: h0 fragments = 0, counters = 0
    if (tid < (NB * NH / 2) / 4) {
        ((uint4*)g_hA[0])[tid] = make_uint4(0u, 0u, 0u, 0u);
    }
    if (tid < GRID2 * 8) { g_flags[tid] = 0u; g_rd[tid] = 0u; }
}

// ---------------------------------------------------------------------------
// Phase 1: gate preactivations, fp16 MMA. 3-stage cp.async pipeline.
// M=32768, N=4096, K=1024, k64 per iter (16 iters). Block 128x128, 256 thr.
// ---------------------------------------------------------------------------
#define P1_SA 36
#define P1_SB 136
#define P1_SMEM ((3 * 128 * P1_SA + 3 * 32 * P1_SB) * 4)

__global__ void __launch_bounds__(256, 2) lstm_xproj(
    const float* __restrict__ bi, const float* __restrict__ bf,
    const float* __restrict__ bc, const float* __restrict__ bo)
{
    extern __shared__ unsigned p1s[];
    unsigned* As = p1s;                        // [3][128][P1_SA]
    unsigned* Bs = p1s + 3 * 128 * P1_SA;      // [3][32][P1_SB]

    const int tid  = threadIdx.x;
    const int lane = tid & 31;
    const int w    = tid >> 5;
    const int mi   = w & 1;
    const int nj   = w >> 1;

    const int mblk  = blockIdx.y;
    const int nglob = blockIdx.x * 128;
    const int gate  = nglob >> 10;
    const int hbase = nglob & 1023;

    const float* bias = (gate == 0) ? bi : (gate == 1) ? bf : (gate == 2) ? bc : bo;

    const int a_row = tid >> 3, a_seg = tid & 7;
    const int b_k2  = tid >> 5, b_seg = tid & 31;
    const unsigned As_u = (unsigned)__cvta_generic_to_shared(As);
    const unsigned Bs_u = (unsigned)__cvta_generic_to_shared(Bs);

    const unsigned* Wg = g_Wh + gate * 524288;

    float acc[4][4][4];
#pragma unroll
    for (int a = 0; a < 4; a++)
#pragma unroll
        for (int b = 0; b < 4; b++)
#pragma unroll
            for (int c = 0; c < 4; c++) acc[a][b][c] = 0.0f;

    // prologue: prefetch tiles 0 and 1 into stages 0,1
#pragma unroll
    for (int pk = 0; pk < 2; pk++) {
#pragma unroll
        for (int i = 0; i < 4; i++) {
            int row = a_row + 32 * i;
            cp16(As_u + (pk * 128 * P1_SA + row * P1_SA + a_seg * 4) * 4,
                 g_xh + (size_t)(mblk * 128 + row) * 512 + pk * 32 + a_seg * 4);
            int k2 = b_k2 + 8 * i;
            cp16(Bs_u + (pk * 32 * P1_SB + k2 * P1_SB + b_seg * 4) * 4,
                 Wg + (size_t)(pk * 32 + k2) * 1024 + hbase + b_seg * 4);
        }
        asm volatile("cp.async.commit_group;\n");
    }

#pragma unroll 1
    for (int kt = 0; kt < 16; ++kt) {
        asm volatile("cp.async.wait_group 1;\n");   // oldest outstanding (tile kt) done
        __syncthreads();

        if (kt + 2 < 16) {
            int s = (kt + 2) % 3;
#pragma unroll
            for (int i = 0; i < 4; i++) {
                int row = a_row + 32 * i;
                cp16(As_u + (s * 128 * P1_SA + row * P1_SA + a_seg * 4) * 4,
                     g_xh + (size_t)(mblk * 128 + row) * 512 + (kt + 2) * 32 + a_seg * 4);
                int k2 = b_k2 + 8 * i;
                cp16(Bs_u + (s * 32 * P1_SB + k2 * P1_SB + b_seg * 4) * 4,
                     Wg + (size_t)((kt + 2) * 32 + k2) * 1024 + hbase + b_seg * 4);
            }
            asm volatile("cp.async.commit_group;\n");
        } else {
            asm volatile("cp.async.commit_group;\n");   // keep group count in sync
        }

        const unsigned* Ab = As + (kt % 3) * 128 * P1_SA;
        const unsigned* Bb = Bs + (kt % 3) * 32 * P1_SB;

#pragma unroll
        for (int q = 0; q < 4; q++) {
            unsigned afr[4][4], bfr[4][2];
#pragma unroll
            for (int mt = 0; mt < 4; mt++) {
                int r = mi * 64 + mt * 16 + (lane >> 2);
                int cw = q * 8 + (lane & 3);
                afr[mt][0] = Ab[r * P1_SA + cw];
                afr[mt][1] = Ab[(r + 8) * P1_SA + cw];
                afr[mt][2] = Ab[r * P1_SA + cw + 4];
                afr[mt][3] = Ab[(r + 8) * P1_SA + cw + 4];
            }
#pragma unroll
            for (int nt = 0; nt < 4; nt++) {
                int nb = nj * 32 + nt * 8 + (lane >> 2);
                bfr[nt][0] = Bb[(q * 8 + (lane & 3)) * P1_SB + nb];
                bfr[nt][1] = Bb[(q * 8 + 4 + (lane & 3)) * P1_SB + nb];
            }
#pragma unroll
            for (int mt = 0; mt < 4; mt++)
#pragma unroll
                for (int nt = 0; nt < 4; nt++)
                    mma16(acc[mt][nt], afr[mt], bfr[nt]);
        }
    }

    float* gbuf = g_gates + (size_t)gate * GATE_STRIDE;
#pragma unroll
    for (int mt = 0; mt < 4; mt++) {
#pragma unroll
        for (int nt = 0; nt < 4; nt++) {
#pragma unroll
            for (int rr = 0; rr < 2; rr++) {
                int m   = mblk * 128 + mi * 64 + mt * 16 + (lane >> 2) + rr * 8;
                int col = nj * 32 + nt * 8 + (lane & 3) * 2;
                int h   = hbase + col;
                int b   = m >> 9;
                int t   = m & 511;
                float2 o;
                o.x = acc[mt][nt][rr * 2 + 0] + __ldg(bias + h);
                o.y = acc[mt][nt][rr * 2 + 1] + __ldg(bias + h + 1);
                *(float2*)(gbuf + (size_t)t * 65536 + (size_t)b * 1024 + h) = o;
            }
        }
    }
}

// ---------------------------------------------------------------------------
// Phase 2: persistent recurrence, fp16 MMA, dataflow-synced.
// CHANGES vs r12: per-warp counter releases (red.add.release) replace the
// sync-C + tid0 publish tail; rd arrivals per warp right after GEMM.
// Flags/rd are counters: value 16*(s+1) once all 16 warps arrived for step s.
// ---------------------------------------------------------------------------
#define P2_SW 40
#define P2_SZ 40
#define SMEM2_BYTES ((512 * P2_SW + 4 * 64 * P2_SZ) * 4)

__global__ void __launch_bounds__(512, 1) lstm_rec(
    const float* __restrict__ Whi, const float* __restrict__ Whf,
    const float* __restrict__ Whc, const float* __restrict__ Who,
    float* __restrict__ out)
{
    extern __shared__ unsigned char smem_raw[];
    unsigned* Wsm  = (unsigned*)smem_raw;            // [512][40]  half2 words, k-paired
    float*    zred = (float*)(Wsm + 512 * P2_SW);    // [4][64][40]

    const int tid  = threadIdx.x;
    const int lane = tid & 31;
    const int w    = tid >> 5;
    const int wm   = w & 1;    // m-half
    const int kg   = w >> 1;   // K-group
    const int blk  = blockIdx.x;
    const int hb   = blk * 8;

    // weight slice -> SMEM as half2 (k, k+1) pairs, once
    {
        const float* Wg[4] = {Whi, Whf, Whc, Who};
        for (int idx = tid; idx < 2048; idx += 512) {
            int g = idx >> 9, k2 = idx & 511;
            const float* s0 = Wg[g] + (size_t)(2 * k2) * 1024 + hb;
            const float* s1 = s0 + 1024;
            float4 a0 = *(const float4*)(s0);
            float4 a1 = *(const float4*)(s0 + 4);
            float4 b0 = *(const float4*)(s1);
            float4 b1 = *(const float4*)(s1 + 4);
            unsigned* d = &Wsm[k2 * P2_SW + g * 8];
            d[0] = h2u(__floats2half2_rn(a0.x, b0.x));
            d[1] = h2u(__floats2half2_rn(a0.y, b0.y));
            d[2] = h2u(__floats2half2_rn(a0.z, b0.z));
            d[3] = h2u(__floats2half2_rn(a0.w, b0.w));
            d[4] = h2u(__floats2half2_rn(a1.x, b1.x));
            d[5] = h2u(__floats2half2_rn(a1.y, b1.y));
            d[6] = h2u(__floats2half2_rn(a1.z, b1.z));
            d[7] = h2u(__floats2half2_rn(a1.w, b1.w));
        }
    }

    // a-frag layout (half2 words): word = ((kg*8+q)*4 + wm*2 + mt)*128 + lane*4 + j
    const int cbase = kg * 4096 + wm * 256 + lane * 4;

    // flag poll: warp kg's producers are CTAs [kg*16, +16)
    const unsigned* fp = g_flags + (kg * 16 + (lane & 15)) * 8;

    // elementwise coords + producer half-scatter index
    const int em = tid >> 3, ej = tid & 7;
    const int hcol = hb + ej;
    int p_hidx;
    {
        int r = em, c = hcol;
        int pkg = c >> 7, c7 = c & 127;
        int pq = c7 >> 4, k16 = c7 & 15;
        int pwm = r >> 5, pmt = (r >> 4) & 1, hi_r = (r >> 3) & 1, lr = r & 7;
        int hi_k = k16 >> 3, l3k = (k16 >> 1) & 3;
        int word = ((pkg * 8 + pq) * 4 + pwm * 2 + pmt) * 128
                 + (lr * 4 + l3k) * 4 + (hi_r + 2 * hi_k);
        p_hidx = word * 2 + (k16 & 1);
    }

    const int l3  = lane & 3;
    const int nbb = lane >> 2;
    float creg = 0.0f;

    __syncthreads();

#pragma unroll 1
    for (int t = 0; t < NT; ++t) {
        const unsigned* hA = g_hA[t & 1];
        __half*         hN = (__half*)g_hA[(t + 1) & 1];

        // prefetch this step's gate preactivations (issued before the wait)
        const size_t gidx = (size_t)t * 65536 + (size_t)em * 1024 + hcol;
        const float gi = __ldg(g_gates + gidx);
        const float gf = __ldg(g_gates + GATE_STRIDE + gidx);
        const float gc = __ldg(g_gates + 2u * GATE_STRIDE + gidx);
        const float go = __ldg(g_gates + 3u * GATE_STRIDE + gidx);

        // ---- forward wait: counters of 16 producers must reach 16*t ----
        const int need = 16 * t;
        for (;;) {
            unsigned v = ld_acq(fp);
            if (__all_sync(0xffffffffu, (int)v >= need)) break;
        }

        float acc[2][4][4];
#pragma unroll
        for (int a = 0; a < 2; a++)
#pragma unroll
            for (int b = 0; b < 4; b++)
#pragma unroll
                for (int c = 0; c < 4; c++) acc[a][b][c] = 0.0f;

        // a-frag pipeline, depth 4 over 8 q-steps (2 LDG.128 per q)
        uint4 abuf[4][2];
#pragma unroll
        for (int p = 0; p < 4; p++) {
            abuf[p][0] = __ldcg((const uint4*)(hA + cbase + p * 512));
            abuf[p][1] = __ldcg((const uint4*)(hA + cbase + p * 512 + 128));
        }

#pragma unroll
        for (int q = 0; q < 8; ++q) {
            const uint4 av0 = abuf[q & 3][0];
            const uint4 av1 = abuf[q & 3][1];
            if (q + 4 < 8) {
                abuf[q & 3][0] = __ldcg((const uint4*)(hA + cbase + (q + 4) * 512));
                abuf[q & 3][1] = __ldcg((const uint4*)(hA + cbase + (q + 4) * 512 + 128));
            }

            const unsigned* wr0 = Wsm + (kg * 64 + q * 8 + l3) * P2_SW;
            const unsigned* wr1 = Wsm + (kg * 64 + q * 8 + 4 + l3) * P2_SW;
            unsigned bfr[4][2];
#pragma unroll
            for (int nt = 0; nt < 4; nt++) {
                bfr[nt][0] = wr0[nt * 8 + nbb];
                bfr[nt][1] = wr1[nt * 8 + nbb];
            }

            {
                unsigned afr0[4] = {av0.x, av0.y, av0.z, av0.w};
                unsigned afr1[4] = {av1.x, av1.y, av1.z, av1.w};
#pragma unroll
                for (int nt = 0; nt < 4; nt++) {
                    mma16(acc[0][nt], afr0, bfr[nt]);
                    mma16(acc[1][nt], afr1, bfr[nt]);
                }
            }
        }

        // ---- per-warp "done reading h(t)" arrival (earliest possible) ----
        __syncwarp();
        if (lane == 0) red_rel(&g_rd[blk * 8], 1u);

        // ---- reduction: even K-groups store, odd RMW (buf = kg>>1) ----
        float* z = zred + (kg >> 1) * 64 * P2_SZ;
        if (!(kg & 1)) {
#pragma unroll
            for (int mt = 0; mt < 2; mt++)
#pragma unroll
                for (int nt = 0; nt < 4; nt++)
#pragma unroll
                    for (int rr = 0; rr < 2; rr++) {
                        int r = wm * 32 + mt * 16 + (lane >> 2) + rr * 8;
                        int c = nt * 8 + (lane & 3) * 2;
                        *(float2*)&z[r * P2_SZ + c] =
                            make_float2(acc[mt][nt][rr * 2], acc[mt][nt][rr * 2 + 1]);
                    }
        }
        __syncthreads();   // sync A

        if (kg & 1) {
#pragma unroll
            for (int mt = 0; mt < 2; mt++)
#pragma unroll
                for (int nt = 0; nt < 4; nt++)
#pragma unroll
                    for (int rr = 0; rr < 2; rr++) {
                        int r = wm * 32 + mt * 16 + (lane >> 2) + rr * 8;
                        int c = nt * 8 + (lane & 3) * 2;
                        float2 old = *(float2*)&z[r * P2_SZ + c];
                        old.x += acc[mt][nt][rr * 2];
                        old.y += acc[mt][nt][rr * 2 + 1];
                        *(float2*)&z[r * P2_SZ + c] = old;
                    }
        }
        // WAR gate: all CTAs done reading h(t-1) (counter >= 16*t) before we
        // overwrite its buffer with h(t+1). Overlaps the odd-RMW phase.
        if (tid < GRID2) {
            while ((int)ld_acq(&g_rd[tid * 8]) < need) { }
        }
        __syncthreads();   // sync B

        // ---- elementwise LSTM cell update ----
        {
            const int zi_idx = em * P2_SZ + ej;
            const int ZB = 64 * P2_SZ;
            float zi = zred[zi_idx]           + zred[ZB + zi_idx]
                     + zred[2 * ZB + zi_idx]  + zred[3 * ZB + zi_idx] + gi;
            float zf = zred[zi_idx + 8]           + zred[ZB + zi_idx + 8]
                     + zred[2 * ZB + zi_idx + 8]  + zred[3 * ZB + zi_idx + 8] + gf;
            float zc = zred[zi_idx + 16]          + zred[ZB + zi_idx + 16]
                     + zred[2 * ZB + zi_idx + 16] + zred[3 * ZB + zi_idx + 16] + gc;
            float zo = zred[zi_idx + 24]          + zred[ZB + zi_idx + 24]
                     + zred[2 * ZB + zi_idx + 24] + zred[3 * ZB + zi_idx + 24] + go;
            float iv = sig_f(zi);
            float fv = sig_f(zf);
            float cv = tanh_f(zc);
            float ov = sig_f(zo);
            float cnew = fv * creg + iv * cv;
            creg = cnew;
            float hv = ov * tanh_f(cnew);
            hN[p_hidx] = __float2half_rn(hv);
            out[(size_t)em * 524288 + (size_t)t * 1024 + hcol] = hv;
            if (t == NT - 1) {
                out[33554432u + (size_t)em * 1024 + hcol] = hv;
                out[33554432u + 65536u + (size_t)em * 1024 + hcol] = cnew;
            }
        }

        // ---- per-warp release: this warp's slice of h(t+1) is written ----
        __syncwarp();
        if (lane == 0) red_rel(&g_flags[blk * 8], 1u);
        // NO sync C: next iteration's __syncthreads (sync A) provides the
        // intra-CTA separation; zred reuse is protected by sync A/B.
    }
}

// ---------------------------------------------------------------------------
extern "C" void kernel_launch(void* const* d_in, const int* in_sizes, int n_in,
                              void* d_out, int out_size)
{
    const float* x   = (const float*)d_in[0];
    const float* Wxi = (const float*)d_in[1];
    const float* Whi = (const float*)d_in[2];
    const float* bi  = (const float*)d_in[3];
    const float* Wxf = (const float*)d_in[4];
    const float* Whf = (const float*)d_in[5];
    const float* bf  = (const float*)d_in[6];
    const float* Wxc = (const float*)d_in[7];
    const float* Whc = (const float*)d_in[8];
    const float* bc  = (const float*)d_in[9];
    const float* Wxo = (const float*)d_in[10];
    const float* Who = (const float*)d_in[11];
    const float* bo  = (const float*)d_in[12];
    float* out = (float*)d_out;

    cudaFuncSetAttribute(lstm_xproj, cudaFuncAttributeMaxDynamicSharedMemorySize, P1_SMEM);
    cudaFuncSetAttribute(lstm_rec,   cudaFuncAttributeMaxDynamicSharedMemorySize, SMEM2_BYTES);

    lstm_conv<<<1024, 256>>>(x, Wxi, Wxf, Wxc, Wxo);

    dim3 g1(32, 256);
    lstm_xproj<<<g1, 256, P1_SMEM>>>(bi, bf, bc, bo);

    lstm_rec<<<GRID2, 512, SMEM2_BYTES>>>(Whi, Whf, Whc, Who, out);
}

// round 15
// speedup vs baseline: 1.0592x; 1.0592x over previous
#include <cuda_runtime.h>
#include <cuda_fp16.h>
#include <cstdint>
#include <cstddef>

#define NB 64
#define NT 512
#define NH 1024
#define GRID2 128

#define GATE_STRIDE 33554432u  // 512*64*1024

__device__ float    g_gates[4u * GATE_STRIDE];  // [gate][t][b][h]
__device__ unsigned g_hA[2][NB * NH / 2];       // h as fp16 pairs, MMA-fragment order
__device__ unsigned g_flags[GRID2 * 8];         // per-CTA "h(v) written" flags
__device__ unsigned g_rd[GRID2 * 8];            // per-CTA "h(v) consumed" flags
__device__ unsigned g_xh[16777216];             // x as half2 (33.5M halves, row-major)
__device__ unsigned g_Wh[2097152];              // W_x as half2 k-pairs: [gate][k2:512][n:1024]

__device__ __forceinline__ unsigned h2u(__half2 h) {
    unsigned u;
    __builtin_memcpy(&u, &h, 4);
    return u;
}

// fp16 m16n8k16
__device__ __forceinline__ void mma16(float c[4], const unsigned a[4], const unsigned b[2]) {
    asm volatile(
        "mma.sync.aligned.m16n8k16.row.col.f32.f16.f16.f32 "
        "{%0,%1,%2,%3},{%4,%5,%6,%7},{%8,%9},{%0,%1,%2,%3};\n"
        : "+f"(c[0]), "+f"(c[1]), "+f"(c[2]), "+f"(c[3])
        : "r"(a[0]), "r"(a[1]), "r"(a[2]), "r"(a[3]), "r"(b[0]), "r"(b[1]));
}

__device__ __forceinline__ void cp16(unsigned dst, const void* src) {
    asm volatile("cp.async.ca.shared.global [%0], [%1], 16;\n" :: "r"(dst), "l"(src));
}

__device__ __forceinline__ unsigned ld_acq(const unsigned* p) {
    unsigned v;
    asm volatile("ld.acquire.gpu.global.u32 %0, [%1];" : "=r"(v) : "l"(p) : "memory");
    return v;
}

__device__ __forceinline__ float sig_f(float z) {
    return __fdividef(1.0f, 1.0f + __expf(-z));
}
__device__ __forceinline__ float tanh_f(float z) {
    return __fdividef(2.0f, 1.0f + __expf(-2.0f * z)) - 1.0f;
}

// ---------------------------------------------------------------------------
// Phase 0: convert x and W_x to fp16 scratch; per-replay init. (r12 exact)
// ---------------------------------------------------------------------------
__global__ void __launch_bounds__(256) lstm_conv(
    const float* __restrict__ x,
    const float* __restrict__ Wxi, const float* __restrict__ Wxf,
    const float* __restrict__ Wxc, const float* __restrict__ Wxo)
{
    const int tid    = blockIdx.x * blockDim.x + threadIdx.x;
    const int stride = gridDim.x * blockDim.x;

    const float2* x2 = (const float2*)x;
#pragma unroll 4
    for (int i = tid; i < 16777216; i += stride) {
        float2 v = x2[i];
        g_xh[i] = h2u(__floats2half2_rn(v.x, v.y));
    }

    for (int i = tid; i < 2097152; i += stride) {
        int g  = i >> 19;
        int r  = i & 524287;
        int k2 = r >> 10;
        int n  = r & 1023;
        const float* W = (g == 0) ? Wxi : (g == 1) ? Wxf : (g == 2) ? Wxc : Wxo;
        float lo = W[(size_t)(2 * k2) * 1024 + n];
        float hi = W[(size_t)(2 * k2 + 1) * 1024 + n];
        g_Wh[i] = h2u(__floats2half2_rn(lo, hi));
    }

    if (tid < (NB * NH / 2) / 4) {
        ((uint4*)g_hA[0])[tid] = make_uint4(0u, 0u, 0u, 0u);
    }
    if (tid < GRID2 * 8) { g_flags[tid] = 0u; g_rd[tid] = 0u; }
}

// ---------------------------------------------------------------------------
// Phase 1: gate preactivations, fp16 MMA (r12 exact: 2-stage cp.async)
// ---------------------------------------------------------------------------
#define P1_SA 36
#define P1_SB 136
#define P1_SMEM ((2 * 128 * P1_SA + 2 * 32 * P1_SB) * 4)

__global__ void __launch_bounds__(256, 2) lstm_xproj(
    const float* __restrict__ bi, const float* __restrict__ bf,
    const float* __restrict__ bc, const float* __restrict__ bo)
{
    extern __shared__ unsigned p1s[];
    unsigned* As = p1s;                        // [2][128][P1_SA]
    unsigned* Bs = p1s + 2 * 128 * P1_SA;      // [2][32][P1_SB]

    const int tid  = threadIdx.x;
    const int lane = tid & 31;
    const int w    = tid >> 5;
    const int mi   = w & 1;
    const int nj   = w >> 1;

    const int mblk  = blockIdx.y;
    const int nglob = blockIdx.x * 128;
    const int gate  = nglob >> 10;
    const int hbase = nglob & 1023;

    const float* bias = (gate == 0) ? bi : (gate == 1) ? bf : (gate == 2) ? bc : bo;

    const int a_row = tid >> 3, a_seg = tid & 7;
    const int b_k2  = tid >> 5, b_seg = tid & 31;
    const unsigned As_u = (unsigned)__cvta_generic_to_shared(As);
    const unsigned Bs_u = (unsigned)__cvta_generic_to_shared(Bs);

    const unsigned* Wg = g_Wh + gate * 524288;

    float acc[4][4][4];
#pragma unroll
    for (int a = 0; a < 4; a++)
#pragma unroll
        for (int b = 0; b < 4; b++)
#pragma unroll
            for (int c = 0; c < 4; c++) acc[a][b][c] = 0.0f;

    {
#pragma unroll
        for (int i = 0; i < 4; i++) {
            int row = a_row + 32 * i;
            cp16(As_u + (row * P1_SA + a_seg * 4) * 4,
                 g_xh + (size_t)(mblk * 128 + row) * 512 + a_seg * 4);
            int k2 = b_k2 + 8 * i;
            cp16(Bs_u + (k2 * P1_SB + b_seg * 4) * 4,
                 Wg + (size_t)k2 * 1024 + hbase + b_seg * 4);
        }
        asm volatile("cp.async.commit_group;\n");
    }

#pragma unroll 1
    for (int kt = 0; kt < 16; ++kt) {
        asm volatile("cp.async.wait_group 0;\n");
        __syncthreads();

        if (kt + 1 < 16) {
            int s = (kt + 1) & 1;
#pragma unroll
            for (int i = 0; i < 4; i++) {
                int row = a_row + 32 * i;
                cp16(As_u + (s * 128 * P1_SA + row * P1_SA + a_seg * 4) * 4,
                     g_xh + (size_t)(mblk * 128 + row) * 512 + (kt + 1) * 32 + a_seg * 4);
                int k2 = b_k2 + 8 * i;
                cp16(Bs_u + (s * 32 * P1_SB + k2 * P1_SB + b_seg * 4) * 4,
                     Wg + (size_t)((kt + 1) * 32 + k2) * 1024 + hbase + b_seg * 4);
            }
            asm volatile("cp.async.commit_group;\n");
        }

        const unsigned* Ab = As + (kt & 1) * 128 * P1_SA;
        const unsigned* Bb = Bs + (kt & 1) * 32 * P1_SB;

#pragma unroll
        for (int q = 0; q < 4; q++) {
            unsigned afr[4][4], bfr[4][2];
#pragma unroll
            for (int mt = 0; mt < 4; mt++) {
                int r = mi * 64 + mt * 16 + (lane >> 2);
                int cw = q * 8 + (lane & 3);
                afr[mt][0] = Ab[r * P1_SA + cw];
                afr[mt][1] = Ab[(r + 8) * P1_SA + cw];
                afr[mt][2] = Ab[r * P1_SA + cw + 4];
                afr[mt][3] = Ab[(r + 8) * P1_SA + cw + 4];
            }
#pragma unroll
            for (int nt = 0; nt < 4; nt++) {
                int nb = nj * 32 + nt * 8 + (lane >> 2);
                bfr[nt][0] = Bb[(q * 8 + (lane & 3)) * P1_SB + nb];
                bfr[nt][1] = Bb[(q * 8 + 4 + (lane & 3)) * P1_SB + nb];
            }
#pragma unroll
            for (int mt = 0; mt < 4; mt++)
#pragma unroll
                for (int nt = 0; nt < 4; nt++)
                    mma16(acc[mt][nt], afr[mt], bfr[nt]);
        }
    }

    float* gbuf = g_gates + (size_t)gate * GATE_STRIDE;
#pragma unroll
    for (int mt = 0; mt < 4; mt++) {
#pragma unroll
        for (int nt = 0; nt < 4; nt++) {
#pragma unroll
            for (int rr = 0; rr < 2; rr++) {
                int m   = mblk * 128 + mi * 64 + mt * 16 + (lane >> 2) + rr * 8;
                int col = nj * 32 + nt * 8 + (lane & 3) * 2;
                int h   = hbase + col;
                int b   = m >> 9;
                int t   = m & 511;
                float2 o;
                o.x = acc[mt][nt][rr * 2 + 0] + __ldg(bias + h);
                o.y = acc[mt][nt][rr * 2 + 1] + __ldg(bias + h + 1);
                *(float2*)(gbuf + (size_t)t * 65536 + (size_t)b * 1024 + h) = o;
            }
        }
    }
}

// ---------------------------------------------------------------------------
// Phase 2: persistent recurrence (r12 skeleton). ONE change vs r12:
// single-phase reduction into 8 zred buffers (one per K-group) — removes
// the odd-warp SMEM RMW from the sync-A..sync-B window; elementwise sums
// 8 partials. Sync structure, flags, ring: r12 exact.
// ---------------------------------------------------------------------------
#define P2_SW 40
#define P2_SZ 40
#define SMEM2_BYTES ((512 * P2_SW + 8 * 64 * P2_SZ) * 4)

__global__ void __launch_bounds__(512, 1) lstm_rec(
    const float* __restrict__ Whi, const float* __restrict__ Whf,
    const float* __restrict__ Whc, const float* __restrict__ Who,
    float* __restrict__ out)
{
    extern __shared__ unsigned char smem_raw[];
    unsigned* Wsm  = (unsigned*)smem_raw;            // [512][40]  half2 words, k-paired
    float*    zred = (float*)(Wsm + 512 * P2_SW);    // [8][64][40]

    const int tid  = threadIdx.x;
    const int lane = tid & 31;
    const int w    = tid >> 5;
    const int wm   = w & 1;    // m-half: rows [wm*32, +32)
    const int kg   = w >> 1;   // K-group: k in [kg*128, +128)
    const int blk  = blockIdx.x;
    const int hb   = blk * 8;

    // weight slice -> SMEM as half2 (k, k+1) pairs, once
    {
        const float* Wg[4] = {Whi, Whf, Whc, Who};
        for (int idx = tid; idx < 2048; idx += 512) {
            int g = idx >> 9, k2 = idx & 511;
            const float* s0 = Wg[g] + (size_t)(2 * k2) * 1024 + hb;
            const float* s1 = s0 + 1024;
            float4 a0 = *(const float4*)(s0);
            float4 a1 = *(const float4*)(s0 + 4);
            float4 b0 = *(const float4*)(s1);
            float4 b1 = *(const float4*)(s1 + 4);
            unsigned* d = &Wsm[k2 * P2_SW + g * 8];
            d[0] = h2u(__floats2half2_rn(a0.x, b0.x));
            d[1] = h2u(__floats2half2_rn(a0.y, b0.y));
            d[2] = h2u(__floats2half2_rn(a0.z, b0.z));
            d[3] = h2u(__floats2half2_rn(a0.w, b0.w));
            d[4] = h2u(__floats2half2_rn(a1.x, b1.x));
            d[5] = h2u(__floats2half2_rn(a1.y, b1.y));
            d[6] = h2u(__floats2half2_rn(a1.z, b1.z));
            d[7] = h2u(__floats2half2_rn(a1.w, b1.w));
        }
    }

    // a-frag layout (half2 words): word = ((kg*8+q)*4 + wm*2 + mt)*128 + lane*4 + j
    const int cbase = kg * 4096 + wm * 256 + lane * 4;

    // flag poll: warp kg's producers are CTAs [kg*16, +16)
    const unsigned* fp = g_flags + (kg * 16 + (lane & 15)) * 8;

    // elementwise coords + producer half-scatter index
    const int em = tid >> 3, ej = tid & 7;
    const int hcol = hb + ej;
    int p_hidx;
    {
        int r = em, c = hcol;
        int pkg = c >> 7, c7 = c & 127;
        int pq = c7 >> 4, k16 = c7 & 15;
        int pwm = r >> 5, pmt = (r >> 4) & 1, hi_r = (r >> 3) & 1, lr = r & 7;
        int hi_k = k16 >> 3, l3k = (k16 >> 1) & 3;
        int word = ((pkg * 8 + pq) * 4 + pwm * 2 + pmt) * 128
                 + (lr * 4 + l3k) * 4 + (hi_r + 2 * hi_k);
        p_hidx = word * 2 + (k16 & 1);
    }

    const int l3  = lane & 3;
    const int nbb = lane >> 2;
    float creg = 0.0f;

    __syncthreads();

#pragma unroll 1
    for (int t = 0; t < NT; ++t) {
        const unsigned* hA = g_hA[t & 1];
        __half*         hN = (__half*)g_hA[(t + 1) & 1];

        // prefetch this step's gate preactivations
        const size_t gidx = (size_t)t * 65536 + (size_t)em * 1024 + hcol;
        const float gi = __ldg(g_gates + gidx);
        const float gf = __ldg(g_gates + GATE_STRIDE + gidx);
        const float gc = __ldg(g_gates + 2u * GATE_STRIDE + gidx);
        const float go = __ldg(g_gates + 3u * GATE_STRIDE + gidx);

        // ---- forward wait: 16 producers of this warp's K range ----
        for (;;) {
            unsigned v = ld_acq(fp);
            if (__all_sync(0xffffffffu, (int)v >= t)) break;
        }

        float acc[2][4][4];
#pragma unroll
        for (int a = 0; a < 2; a++)
#pragma unroll
            for (int b = 0; b < 4; b++)
#pragma unroll
                for (int c = 0; c < 4; c++) acc[a][b][c] = 0.0f;

        // a-frag pipeline, depth 4 over 8 q-steps (2 LDG.128 per q)
        uint4 abuf[4][2];
#pragma unroll
        for (int p = 0; p < 4; p++) {
            abuf[p][0] = __ldcg((const uint4*)(hA + cbase + p * 512));
            abuf[p][1] = __ldcg((const uint4*)(hA + cbase + p * 512 + 128));
        }

#pragma unroll
        for (int q = 0; q < 8; ++q) {
            const uint4 av0 = abuf[q & 3][0];
            const uint4 av1 = abuf[q & 3][1];
            if (q + 4 < 8) {
                abuf[q & 3][0] = __ldcg((const uint4*)(hA + cbase + (q + 4) * 512));
                abuf[q & 3][1] = __ldcg((const uint4*)(hA + cbase + (q + 4) * 512 + 128));
            }

            const unsigned* wr0 = Wsm + (kg * 64 + q * 8 + l3) * P2_SW;
            const unsigned* wr1 = Wsm + (kg * 64 + q * 8 + 4 + l3) * P2_SW;
            unsigned bfr[4][2];
#pragma unroll
            for (int nt = 0; nt < 4; nt++) {
                bfr[nt][0] = wr0[nt * 8 + nbb];
                bfr[nt][1] = wr1[nt * 8 + nbb];
            }

            {
                unsigned afr0[4] = {av0.x, av0.y, av0.z, av0.w};
                unsigned afr1[4] = {av1.x, av1.y, av1.z, av1.w};
#pragma unroll
                for (int nt = 0; nt < 4; nt++) {
                    mma16(acc[0][nt], afr0, bfr[nt]);
                    mma16(acc[1][nt], afr1, bfr[nt]);
                }
            }
        }

        // ---- single-phase reduction: every K-group stores to its own buffer ----
        {
            float* z = zred + kg * 64 * P2_SZ;
#pragma unroll
            for (int mt = 0; mt < 2; mt++)
#pragma unroll
                for (int nt = 0; nt < 4; nt++)
#pragma unroll
                    for (int rr = 0; rr < 2; rr++) {
                        int r = wm * 32 + mt * 16 + (lane >> 2) + rr * 8;
                        int c = nt * 8 + (lane & 3) * 2;
                        *(float2*)&z[r * P2_SZ + c] =
                            make_float2(acc[mt][nt][rr * 2], acc[mt][nt][rr * 2 + 1]);
                    }
        }
        __syncthreads();   // sync A: all h(t) reads complete, all partials visible

        // publish "h(t) consumed" (r12 scheme)
        if (tid == 0)
            *(volatile unsigned*)&g_rd[blk * 8] = (unsigned)(t + 1);

        // WAR gate for 2-buffer ring: all CTAs done reading h(t-1)
        if (tid < GRID2) {
            while ((int)(*(volatile unsigned*)&g_rd[tid * 8]) < t) { }
        }
        __syncthreads();   // sync B

        // ---- elementwise LSTM cell update: sum 8 partials per gate ----
        {
            const int zi_idx = em * P2_SZ + ej;
            const int ZB = 64 * P2_SZ;
            float zi = gi, zf = gf, zc = gc, zo = go;
#pragma unroll
            for (int b = 0; b < 8; b++) {
                const float* zb = zred + b * ZB + zi_idx;
                zi += zb[0];
                zf += zb[8];
                zc += zb[16];
                zo += zb[24];
            }
            float iv = sig_f(zi);
            float fv = sig_f(zf);
            float cv = tanh_f(zc);
            float ov = sig_f(zo);
            float cnew = fv * creg + iv * cv;
            creg = cnew;
            float hv = ov * tanh_f(cnew);
            hN[p_hidx] = __float2half_rn(hv);
            out[(size_t)em * 524288 + (size_t)t * 1024 + hcol] = hv;
            if (t == NT - 1) {
                out[33554432u + (size_t)em * 1024 + hcol] = hv;
                out[33554432u + 65536u + (size_t)em * 1024 + hcol] = cnew;
            }
        }

        // ---- release: h(t+1) of this CTA available (r12 scheme) ----
        __syncthreads();   // sync C
        if (tid == 0) {
            __threadfence();
            *(volatile unsigned*)&g_flags[blk * 8] = (unsigned)(t + 1);
        }
    }
}

// ---------------------------------------------------------------------------
extern "C" void kernel_launch(void* const* d_in, const int* in_sizes, int n_in,
                              void* d_out, int out_size)
{
    const float* x   = (const float*)d_in[0];
    const float* Wxi = (const float*)d_in[1];
    const float* Whi = (const float*)d_in[2];
    const float* bi  = (const float*)d_in[3];
    const float* Wxf = (const float*)d_in[4];
    const float* Whf = (const float*)d_in[5];
    const float* bf  = (const float*)d_in[6];
    const float* Wxc = (const float*)d_in[7];
    const float* Whc = (const float*)d_in[8];
    const float* bc  = (const float*)d_in[9];
    const float* Wxo = (const float*)d_in[10];
    const float* Who = (const float*)d_in[11];
    const float* bo  = (const float*)d_in[12];
    float* out = (float*)d_out;

    cudaFuncSetAttribute(lstm_xproj, cudaFuncAttributeMaxDynamicSharedMemorySize, P1_SMEM);
    cudaFuncSetAttribute(lstm_rec,   cudaFuncAttributeMaxDynamicSharedMemorySize, SMEM2_BYTES);

    lstm_conv<<<1024, 256>>>(x, Wxi, Wxf, Wxc, Wxo);

    dim3 g1(32, 256);
    lstm_xproj<<<g1, 256, P1_SMEM>>>(bi, bf, bc, bo);

    lstm_rec<<<GRID2, 512, SMEM2_BYTES>>>(Whi, Whf, Whc, Who, out);
}

// round 16
// speedup vs baseline: 1.1577x; 1.0930x over previous
#include <cuda_runtime.h>
#include <cuda_fp16.h>
#include <cstdint>
#include <cstddef>

#define NB 64
#define NT 512
#define NH 1024
#define GRID2 128

#define GATE_STRIDE 33554432u  // 512*64*1024

__device__ float    g_gates[4u * GATE_STRIDE];  // [gate][t][b][h]
__device__ unsigned g_hA[2][32768];             // h fp16 frags: [buf][group*16384 + word]
__device__ unsigned g_flags[GRID2 * 8];         // per-CTA "h(v) written" flags
__device__ unsigned g_rd[GRID2 * 8];            // per-CTA "h(v) consumed" flags
__device__ unsigned g_xh[16777216];             // x as half2
__device__ unsigned g_Wh[2097152];              // W_x as half2 k-pairs: [gate][k2:512][n:1024]

__device__ __forceinline__ unsigned h2u(__half2 h) {
    unsigned u;
    __builtin_memcpy(&u, &h, 4);
    return u;
}

// fp16 m16n8k16
__device__ __forceinline__ void mma16(float c[4], const unsigned a[4], const unsigned b[2]) {
    asm volatile(
        "mma.sync.aligned.m16n8k16.row.col.f32.f16.f16.f32 "
        "{%0,%1,%2,%3},{%4,%5,%6,%7},{%8,%9},{%0,%1,%2,%3};\n"
        : "+f"(c[0]), "+f"(c[1]), "+f"(c[2]), "+f"(c[3])
        : "r"(a[0]), "r"(a[1]), "r"(a[2]), "r"(a[3]), "r"(b[0]), "r"(b[1]));
}

__device__ __forceinline__ void cp16(unsigned dst, const void* src) {
    asm volatile("cp.async.ca.shared.global [%0], [%1], 16;\n" :: "r"(dst), "l"(src));
}

__device__ __forceinline__ unsigned ld_acq(const unsigned* p) {
    unsigned v;
    asm volatile("ld.acquire.gpu.global.u32 %0, [%1];" : "=r"(v) : "l"(p) : "memory");
    return v;
}

__device__ __forceinline__ float sig_f(float z) {
    return __fdividef(1.0f, 1.0f + __expf(-z));
}
__device__ __forceinline__ float tanh_f(float z) {
    return __fdividef(2.0f, 1.0f + __expf(-2.0f * z)) - 1.0f;
}

// ---------------------------------------------------------------------------
// Phase 0: convert x and W_x to fp16 scratch; per-replay init. (r12 exact,
// h0 zeroing covers both groups)
// ---------------------------------------------------------------------------
__global__ void __launch_bounds__(256) lstm_conv(
    const float* __restrict__ x,
    const float* __restrict__ Wxi, const float* __restrict__ Wxf,
    const float* __restrict__ Wxc, const float* __restrict__ Wxo)
{
    const int tid    = blockIdx.x * blockDim.x + threadIdx.x;
    const int stride = gridDim.x * blockDim.x;

    const float2* x2 = (const float2*)x;
#pragma unroll 4
    for (int i = tid; i < 16777216; i += stride) {
        float2 v = x2[i];
        g_xh[i] = h2u(__floats2half2_rn(v.x, v.y));
    }

    for (int i = tid; i < 2097152; i += stride) {
        int g  = i >> 19;
        int r  = i & 524287;
        int k2 = r >> 10;
        int n  = r & 1023;
        const float* W = (g == 0) ? Wxi : (g == 1) ? Wxf : (g == 2) ? Wxc : Wxo;
        float lo = W[(size_t)(2 * k2) * 1024 + n];
        float hi = W[(size_t)(2 * k2 + 1) * 1024 + n];
        g_Wh[i] = h2u(__floats2half2_rn(lo, hi));
    }

    if (tid < 32768 / 4) {
        ((uint4*)g_hA[0])[tid] = make_uint4(0u, 0u, 0u, 0u);
    }
    if (tid < GRID2 * 8) { g_flags[tid] = 0u; g_rd[tid] = 0u; }
}

// ---------------------------------------------------------------------------
// Phase 1: gate preactivations, fp16 MMA (r12 exact)
// ---------------------------------------------------------------------------
#define P1_SA 36
#define P1_SB 136
#define P1_SMEM ((2 * 128 * P1_SA + 2 * 32 * P1_SB) * 4)

__global__ void __launch_bounds__(256, 2) lstm_xproj(
    const float* __restrict__ bi, const float* __restrict__ bf,
    const float* __restrict__ bc, const float* __restrict__ bo)
{
    extern __shared__ unsigned p1s[];
    unsigned* As = p1s;
    unsigned* Bs = p1s + 2 * 128 * P1_SA;

    const int tid  = threadIdx.x;
    const int lane = tid & 31;
    const int w    = tid >> 5;
    const int mi   = w & 1;
    const int nj   = w >> 1;

    const int mblk  = blockIdx.y;
    const int nglob = blockIdx.x * 128;
    const int gate  = nglob >> 10;
    const int hbase = nglob & 1023;

    const float* bias = (gate == 0) ? bi : (gate == 1) ? bf : (gate == 2) ? bc : bo;

    const int a_row = tid >> 3, a_seg = tid & 7;
    const int b_k2  = tid >> 5, b_seg = tid & 31;
    const unsigned As_u = (unsigned)__cvta_generic_to_shared(As);
    const unsigned Bs_u = (unsigned)__cvta_generic_to_shared(Bs);

    const unsigned* Wg = g_Wh + gate * 524288;

    float acc[4][4][4];
#pragma unroll
    for (int a = 0; a < 4; a++)
#pragma unroll
        for (int b = 0; b < 4; b++)
#pragma unroll
            for (int c = 0; c < 4; c++) acc[a][b][c] = 0.0f;

    {
#pragma unroll
        for (int i = 0; i < 4; i++) {
            int row = a_row + 32 * i;
            cp16(As_u + (row * P1_SA + a_seg * 4) * 4,
                 g_xh + (size_t)(mblk * 128 + row) * 512 + a_seg * 4);
            int k2 = b_k2 + 8 * i;
            cp16(Bs_u + (k2 * P1_SB + b_seg * 4) * 4,
                 Wg + (size_t)k2 * 1024 + hbase + b_seg * 4);
        }
        asm volatile("cp.async.commit_group;\n");
    }

#pragma unroll 1
    for (int kt = 0; kt < 16; ++kt) {
        asm volatile("cp.async.wait_group 0;\n");
        __syncthreads();

        if (kt + 1 < 16) {
            int s = (kt + 1) & 1;
#pragma unroll
            for (int i = 0; i < 4; i++) {
                int row = a_row + 32 * i;
                cp16(As_u + (s * 128 * P1_SA + row * P1_SA + a_seg * 4) * 4,
                     g_xh + (size_t)(mblk * 128 + row) * 512 + (kt + 1) * 32 + a_seg * 4);
                int k2 = b_k2 + 8 * i;
                cp16(Bs_u + (s * 32 * P1_SB + k2 * P1_SB + b_seg * 4) * 4,
                     Wg + (size_t)((kt + 1) * 32 + k2) * 1024 + hbase + b_seg * 4);
            }
            asm volatile("cp.async.commit_group;\n");
        }

        const unsigned* Ab = As + (kt & 1) * 128 * P1_SA;
        const unsigned* Bb = Bs + (kt & 1) * 32 * P1_SB;

#pragma unroll
        for (int q = 0; q < 4; q++) {
            unsigned afr[4][4], bfr[4][2];
#pragma unroll
            for (int mt = 0; mt < 4; mt++) {
                int r = mi * 64 + mt * 16 + (lane >> 2);
                int cw = q * 8 + (lane & 3);
                afr[mt][0] = Ab[r * P1_SA + cw];
                afr[mt][1] = Ab[(r + 8) * P1_SA + cw];
                afr[mt][2] = Ab[r * P1_SA + cw + 4];
                afr[mt][3] = Ab[(r + 8) * P1_SA + cw + 4];
            }
#pragma unroll
            for (int nt = 0; nt < 4; nt++) {
                int nb = nj * 32 + nt * 8 + (lane >> 2);
                bfr[nt][0] = Bb[(q * 8 + (lane & 3)) * P1_SB + nb];
                bfr[nt][1] = Bb[(q * 8 + 4 + (lane & 3)) * P1_SB + nb];
            }
#pragma unroll
            for (int mt = 0; mt < 4; mt++)
#pragma unroll
                for (int nt = 0; nt < 4; nt++)
                    mma16(acc[mt][nt], afr[mt], bfr[nt]);
        }
    }

    float* gbuf = g_gates + (size_t)gate * GATE_STRIDE;
#pragma unroll
    for (int mt = 0; mt < 4; mt++) {
#pragma unroll
        for (int nt = 0; nt < 4; nt++) {
#pragma unroll
            for (int rr = 0; rr < 2; rr++) {
                int m   = mblk * 128 + mi * 64 + mt * 16 + (lane >> 2) + rr * 8;
                int col = nj * 32 + nt * 8 + (lane & 3) * 2;
                int h   = hbase + col;
                int b   = m >> 9;
                int t   = m & 511;
                float2 o;
                o.x = acc[mt][nt][rr * 2 + 0] + __ldg(bias + h);
                o.y = acc[mt][nt][rr * 2 + 1] + __ldg(bias + h + 1);
                *(float2*)(gbuf + (size_t)t * 65536 + (size_t)b * 1024 + h) = o;
            }
        }
    }
}

// ---------------------------------------------------------------------------
// Phase 2: persistent recurrence, BATCH-SPLIT into 2 independent groups.
// Group g (64 CTAs) owns batch rows [g*32, g*32+32). CTA owns h-cols
// [c*16, c*16+16) x 4 gates (N=64) for its group's 32 rows (M=32).
// 16 warps = 8 K-groups x 2 m-halves; warp tile m16 n64 k128.
// L2 h-broadcast: 8 MB/step (halved). Sync skeleton: r12 exact, per-group.
// ---------------------------------------------------------------------------
#define P2_SW 72     // Wsm row stride (words): conflict-free b-frag loads
#define P2_SZ 72
#define SMEM2_BYTES ((512 * P2_SW + 4 * 32 * P2_SZ) * 4)

__global__ void __launch_bounds__(512, 1) lstm_rec(
    const float* __restrict__ Whi, const float* __restrict__ Whf,
    const float* __restrict__ Whc, const float* __restrict__ Who,
    float* __restrict__ out)
{
    extern __shared__ unsigned char smem_raw[];
    unsigned* Wsm  = (unsigned*)smem_raw;            // [512][72] half2 words, k-paired, n=gate*16+j
    float*    zred = (float*)(Wsm + 512 * P2_SW);    // [4][32][72]

    const int tid  = threadIdx.x;
    const int lane = tid & 31;
    const int w    = tid >> 5;
    const int mh   = w & 1;    // m-half: rows [mh*16, +16) of the group's 32
    const int kg   = w >> 1;   // K-group: k in [kg*128, +128)
    const int blk  = blockIdx.x;
    const int grp  = blk >> 6;           // group 0/1
    const int cta  = blk & 63;           // CTA within group
    const int hb   = cta * 16;           // h-col base

    // weight slice -> SMEM: 4 gates x 1024 k x 16 cols, half2 k-pairs.
    // Wsm[k2][n] with n = gate*16 + j.
    {
        const float* Wg[4] = {Whi, Whf, Whc, Who};
        for (int idx = tid; idx < 32768; idx += 512) {   // 4g x 512k2 x 16j
            int g  = idx >> 13;
            int r  = idx & 8191;
            int k2 = r >> 4;
            int j  = r & 15;
            const float* W = Wg[g];
            int col = hb + j;
            float lo = W[(size_t)(2 * k2) * 1024 + col];
            float hi = W[(size_t)(2 * k2 + 1) * 1024 + col];
            Wsm[k2 * P2_SW + g * 16 + j] = h2u(__floats2half2_rn(lo, hi));
        }
    }

    // consumer a-frag base (words, within group buffer):
    // word = ((kg*8+q)*2 + mh)*128 + lane*4 + jw ; q stride 256
    const int cbase = kg * 2048 + mh * 128 + lane * 4;
    const unsigned grp_off = grp * 16384;   // words

    // forward wait: warp kg's producers are group CTAs [kg*8, +8)
    const unsigned* fp = g_flags + ((grp * 64 + kg * 8 + (lane & 7)) * 8);

    // elementwise coords + producer half-scatter index
    const int em2 = tid >> 4;          // local row 0..31
    const int ej  = tid & 15;          // local col 0..15
    const int hcol = hb + ej;          // global h col
    const int row_g = grp * 32 + em2;  // global batch row
    int p_hidx;                        // half index within group buffer
    {
        int r = em2, c = hcol;
        int pkg = c >> 7, c7 = c & 127;
        int pq = c7 >> 4, k16 = c7 & 15;
        int pmh = r >> 4, r15 = r & 15, hi_r = r15 >> 3, lr = r15 & 7;
        int hi_k = k16 >> 3, l3k = (k16 >> 1) & 3;
        int word = ((pkg * 8 + pq) * 2 + pmh) * 128
                 + (lr * 4 + l3k) * 4 + (hi_r + 2 * hi_k);
        p_hidx = word * 2 + (k16 & 1);
    }

    const int l3  = lane & 3;
    const int nbb = lane >> 2;
    float creg = 0.0f;

    __syncthreads();

#pragma unroll 1
    for (int t = 0; t < NT; ++t) {
        const unsigned* hA = g_hA[t & 1] + grp_off;
        __half*         hN = (__half*)(g_hA[(t + 1) & 1] + grp_off);

        // prefetch this step's gate preactivations
        const size_t gidx = (size_t)t * 65536 + (size_t)row_g * 1024 + hcol;
        const float gi = __ldg(g_gates + gidx);
        const float gf = __ldg(g_gates + GATE_STRIDE + gidx);
        const float gc = __ldg(g_gates + 2u * GATE_STRIDE + gidx);
        const float go = __ldg(g_gates + 3u * GATE_STRIDE + gidx);

        // ---- forward wait: 8 producers of this warp's K range ----
        for (;;) {
            unsigned v = ld_acq(fp);
            if (__all_sync(0xffffffffu, (int)v >= t)) break;
        }

        float acc[8][4];
#pragma unroll
        for (int a = 0; a < 8; a++)
#pragma unroll
            for (int c = 0; c < 4; c++) acc[a][c] = 0.0f;

        // a-frag pipeline: 1 uint4 per q, depth 4 over 8 q-steps
        uint4 abuf[4];
#pragma unroll
        for (int p = 0; p < 4; p++)
            abuf[p] = __ldcg((const uint4*)(hA + cbase + p * 256));

#pragma unroll
        for (int q = 0; q < 8; ++q) {
            const uint4 av = abuf[q & 3];
            if (q + 4 < 8)
                abuf[q & 3] = __ldcg((const uint4*)(hA + cbase + (q + 4) * 256));

            // b-frags: k2 rows kg*64 + q*8 + l3 and +4, all 8 n-tiles
            const unsigned* wr0 = Wsm + (kg * 64 + q * 8 + l3) * P2_SW;
            const unsigned* wr1 = Wsm + (kg * 64 + q * 8 + 4 + l3) * P2_SW;
            unsigned afr[4] = {av.x, av.y, av.z, av.w};
#pragma unroll
            for (int nt = 0; nt < 8; nt++) {
                unsigned bfr[2];
                bfr[0] = wr0[nt * 8 + nbb];
                bfr[1] = wr1[nt * 8 + nbb];
                mma16(acc[nt], afr, bfr);
            }
        }

        // ---- two-phase reduction (r12 scheme): kg<4 store, kg>=4 RMW ----
        float* z = zred + (kg & 3) * 32 * P2_SZ;
        if (kg < 4) {
#pragma unroll
            for (int nt = 0; nt < 8; nt++)
#pragma unroll
                for (int rr = 0; rr < 2; rr++) {
                    int r = mh * 16 + (lane >> 2) + rr * 8;
                    int c = nt * 8 + (lane & 3) * 2;
                    *(float2*)&z[r * P2_SZ + c] =
                        make_float2(acc[nt][rr * 2], acc[nt][rr * 2 + 1]);
                }
        }
        __syncthreads();   // sync A: all h(t) reads complete, phase-0 partials visible

        // publish "h(t) consumed"
        if (tid == 0)
            *(volatile unsigned*)&g_rd[blk * 8] = (unsigned)(t + 1);

        if (kg >= 4) {
#pragma unroll
            for (int nt = 0; nt < 8; nt++)
#pragma unroll
                for (int rr = 0; rr < 2; rr++) {
                    int r = mh * 16 + (lane >> 2) + rr * 8;
                    int c = nt * 8 + (lane & 3) * 2;
                    float2 old = *(float2*)&z[r * P2_SZ + c];
                    old.x += acc[nt][rr * 2];
                    old.y += acc[nt][rr * 2 + 1];
                    *(float2*)&z[r * P2_SZ + c] = old;
                }
        }
        // WAR gate: all 64 group CTAs done reading h(t-1)
        if (tid < 64) {
            while ((int)(*(volatile unsigned*)&g_rd[(grp * 64 + tid) * 8]) < t) { }
        }
        __syncthreads();   // sync B

        // ---- elementwise LSTM cell update (1 element / thread) ----
        {
            const int zbase = em2 * P2_SZ + ej;
            const int ZB = 32 * P2_SZ;
            float zi = gi, zf = gf, zc = gc, zo = go;
#pragma unroll
            for (int b = 0; b < 4; b++) {
                const float* zb = zred + b * ZB + zbase;
                zi += zb[0];
                zf += zb[16];
                zc += zb[32];
                zo += zb[48];
            }
            float iv = sig_f(zi);
            float fv = sig_f(zf);
            float cv = tanh_f(zc);
            float ov = sig_f(zo);
            float cnew = fv * creg + iv * cv;
            creg = cnew;
            float hv = ov * tanh_f(cnew);
            hN[p_hidx] = __float2half_rn(hv);
            out[(size_t)row_g * 524288 + (size_t)t * 1024 + hcol] = hv;
            if (t == NT - 1) {
                out[33554432u + (size_t)row_g * 1024 + hcol] = hv;
                out[33554432u + 65536u + (size_t)row_g * 1024 + hcol] = cnew;
            }
        }

        // ---- release: h(t+1) slice of this CTA available ----
        __syncthreads();   // sync C
        if (tid == 0) {
            __threadfence();
            *(volatile unsigned*)&g_flags[blk * 8] = (unsigned)(t + 1);
        }
    }
}

// ---------------------------------------------------------------------------
extern "C" void kernel_launch(void* const* d_in, const int* in_sizes, int n_in,
                              void* d_out, int out_size)
{
    const float* x   = (const float*)d_in[0];
    const float* Wxi = (const float*)d_in[1];
    const float* Whi = (const float*)d_in[2];
    const float* bi  = (const float*)d_in[3];
    const float* Wxf = (const float*)d_in[4];
    const float* Whf = (const float*)d_in[5];
    const float* bf  = (const float*)d_in[6];
    const float* Wxc = (const float*)d_in[7];
    const float* Whc = (const float*)d_in[8];
    const float* bc  = (const float*)d_in[9];
    const float* Wxo = (const float*)d_in[10];
    const float* Who = (const float*)d_in[11];
    const float* bo  = (const float*)d_in[12];
    float* out = (float*)d_out;

    cudaFuncSetAttribute(lstm_xproj, cudaFuncAttributeMaxDynamicSharedMemorySize, P1_SMEM);
    cudaFuncSetAttribute(lstm_rec,   cudaFuncAttributeMaxDynamicSharedMemorySize, SMEM2_BYTES);

    lstm_conv<<<1024, 256>>>(x, Wxi, Wxf, Wxc, Wxo);

    dim3 g1(32, 256);
    lstm_xproj<<<g1, 256, P1_SMEM>>>(bi, bf, bc, bo);

    lstm_rec<<<GRID2, 512, SMEM2_BYTES>>>(Whi, Whf, Whc, Who, out);
}